// round 3
// baseline (speedup 1.0000x reference)
#include <cuda_runtime.h>
#include <cuda_bf16.h>
#include <math.h>

// Fixed problem shapes
#define NMAX   50000
#define FMAX   512
#define GCNT   512
#define FPOUT  2048

// Scratch (device globals: no allocation allowed)
__device__ float g_h[(size_t)NMAX * FMAX];   // GEMM output per layer
__device__ float g_x[(size_t)NMAX * FMAX];   // activation per layer
__device__ float g_deg[NMAX];
__device__ float g_dis[NMAX];
__device__ float g_gate[NMAX];
__device__ float g_pool[GCNT * 1024];
__device__ int   g_start[GCNT];
__device__ int   g_end[GCNT];

// ---------------------------------------------------------------------------
// SGEMM: C[M,N] = A[M,K] @ B[K,N] (+bias, +relu). BM=BN=64, BK=16, 256 thr,
// 4x4 microtile. N,K multiples of 64/16 for all calls; M guarded.
// ---------------------------------------------------------------------------
#define BM 64
#define BN 64
#define BK 16

__global__ void __launch_bounds__(256) sgemm_k(
    const float* __restrict__ A, const float* __restrict__ B,
    float* __restrict__ C, int M, int N, int K,
    const float* __restrict__ bias, int dorelu)
{
    __shared__ float As[BK][BM];
    __shared__ float Bs[BK][BN];
    const int bm = blockIdx.y * BM;
    const int bn = blockIdx.x * BN;
    const int tid = threadIdx.x;
    const int tr = (tid >> 4) << 2;   // 0..60 (row in tile)
    const int tc = (tid & 15) << 2;   // 0..60 (col in tile)
    const int arow = tid >> 2;        // 0..63
    const int acol = (tid & 3) << 2;  // 0,4,8,12
    const int brow = tid >> 4;        // 0..15
    const int bcol = (tid & 15) << 2; // 0..60

    float acc[4][4] = {};

    for (int k0 = 0; k0 < K; k0 += BK) {
        float4 av = make_float4(0.f, 0.f, 0.f, 0.f);
        if (bm + arow < M)
            av = *(const float4*)(A + (size_t)(bm + arow) * K + k0 + acol);
        As[acol + 0][arow] = av.x;
        As[acol + 1][arow] = av.y;
        As[acol + 2][arow] = av.z;
        As[acol + 3][arow] = av.w;
        *(float4*)&Bs[brow][bcol] =
            *(const float4*)(B + (size_t)(k0 + brow) * N + bn + bcol);
        __syncthreads();
#pragma unroll
        for (int k = 0; k < BK; k++) {
            float4 a = *(const float4*)&As[k][tr];
            float4 b = *(const float4*)&Bs[k][tc];
            acc[0][0] += a.x * b.x; acc[0][1] += a.x * b.y; acc[0][2] += a.x * b.z; acc[0][3] += a.x * b.w;
            acc[1][0] += a.y * b.x; acc[1][1] += a.y * b.y; acc[1][2] += a.y * b.z; acc[1][3] += a.y * b.w;
            acc[2][0] += a.z * b.x; acc[2][1] += a.z * b.y; acc[2][2] += a.z * b.z; acc[2][3] += a.z * b.w;
            acc[3][0] += a.w * b.x; acc[3][1] += a.w * b.y; acc[3][2] += a.w * b.z; acc[3][3] += a.w * b.w;
        }
        __syncthreads();
    }

#pragma unroll
    for (int i = 0; i < 4; i++) {
        int row = bm + tr + i;
        if (row >= M) break;
#pragma unroll
        for (int j = 0; j < 4; j++) {
            float v = acc[i][j];
            if (bias) v += bias[bn + tc + j];
            if (dorelu) v = fmaxf(v, 0.f);
            C[(size_t)row * N + bn + tc + j] = v;
        }
    }
}

// ---------------------------------------------------------------------------
// Degree / norm (int32 edge indices — JAX x64 is disabled, int64 -> int32)
// ---------------------------------------------------------------------------
__global__ void deg_init_k(int n) {
    int i = blockIdx.x * blockDim.x + threadIdx.x;
    if (i < n) g_deg[i] = 1.0f;  // self-loop
}
__global__ void deg_edge_k(const int* __restrict__ dst, int e) {
    int i = blockIdx.x * blockDim.x + threadIdx.x;
    if (i < e) atomicAdd(&g_deg[dst[i]], 1.0f);
}
__global__ void dis_k(int n) {
    int i = blockIdx.x * blockDim.x + threadIdx.x;
    if (i < n) g_dis[i] = rsqrtf(g_deg[i]);
}

// ---------------------------------------------------------------------------
// Aggregation: out[i] = h[i]/deg[i]; then out[dst] += h[src]*dis[src]*dis[dst]
// ---------------------------------------------------------------------------
__global__ void self_init_k(const float* __restrict__ h, float* __restrict__ out,
                            int n, int f) {
    int idx = blockIdx.x * blockDim.x + threadIdx.x;
    int nf4 = f >> 2;
    int total = n * nf4;
    if (idx >= total) return;
    int row = idx / nf4;
    float inv = 1.0f / g_deg[row];
    float4 v = ((const float4*)h)[idx];
    v.x *= inv; v.y *= inv; v.z *= inv; v.w *= inv;
    ((float4*)out)[idx] = v;
}

__device__ __forceinline__ void red_add_v4(float4* addr, float4 v) {
    asm volatile("red.global.add.v4.f32 [%0], {%1,%2,%3,%4};"
                 :: "l"(addr), "f"(v.x), "f"(v.y), "f"(v.z), "f"(v.w)
                 : "memory");
}

__global__ void edge_agg_k(const int* __restrict__ src,
                           const int* __restrict__ dst,
                           const float* __restrict__ h, float* __restrict__ out,
                           int e, int f) {
    int w = (blockIdx.x * blockDim.x + threadIdx.x) >> 5;
    if (w >= e) return;
    int lane = threadIdx.x & 31;
    int s = src[w], d = dst[w];
    float nrm = g_dis[s] * g_dis[d];
    const float4* hs = (const float4*)(h + (size_t)s * f);
    float4* od = (float4*)(out + (size_t)d * f);
    int nf4 = f >> 2;
    for (int c = lane; c < nf4; c += 32) {
        float4 v = hs[c];
        v.x *= nrm; v.y *= nrm; v.z *= nrm; v.w *= nrm;
        red_add_v4(od + c, v);
    }
}

__global__ void finalize_k(float* __restrict__ out, const float* __restrict__ bias,
                           int n, int f) {
    int idx = blockIdx.x * blockDim.x + threadIdx.x;
    int nf4 = f >> 2;
    int total = n * nf4;
    if (idx >= total) return;
    int c4 = idx % nf4;
    float4 v = ((float4*)out)[idx];
    float4 b = ((const float4*)bias)[c4];
    v.x = fmaxf(v.x + b.x, 0.f);
    v.y = fmaxf(v.y + b.y, 0.f);
    v.z = fmaxf(v.z + b.z, 0.f);
    v.w = fmaxf(v.w + b.w, 0.f);
    ((float4*)out)[idx] = v;
}

// ---------------------------------------------------------------------------
// Gate: g_gate[i] = sigmoid(dot(x[i], pw) + pb)   (warp per node, F=512)
// ---------------------------------------------------------------------------
__global__ void gate_k(const float* __restrict__ x, const float* __restrict__ pw,
                       const float* __restrict__ pb, int n) {
    int w = (blockIdx.x * blockDim.x + threadIdx.x) >> 5;
    if (w >= n) return;
    int lane = threadIdx.x & 31;
    const float* row = x + (size_t)w * 512;
    float s = 0.f;
#pragma unroll
    for (int c = lane; c < 512; c += 32) s += row[c] * pw[c];
#pragma unroll
    for (int o = 16; o > 0; o >>= 1) s += __shfl_xor_sync(0xffffffffu, s, o);
    if (lane == 0) g_gate[w] = 1.f / (1.f + expf(-(s + pb[0])));
}

// ---------------------------------------------------------------------------
// Segment bounds (batch is sorted) + pooling (block per graph)
// ---------------------------------------------------------------------------
__global__ void seg_init_k(int n) {
    int g = blockIdx.x * blockDim.x + threadIdx.x;
    if (g < GCNT) { g_start[g] = n; g_end[g] = 0; }
}
__global__ void seg_bounds_k(const int* __restrict__ batch, int n) {
    int i = blockIdx.x * blockDim.x + threadIdx.x;
    if (i >= n) return;
    int g = batch[i];
    atomicMin(&g_start[g], i);
    atomicMax(&g_end[g], i + 1);
}
__global__ void __launch_bounds__(512) pool_k(const float* __restrict__ x) {
    int g = blockIdx.x;
    int s = g_start[g], e = g_end[g];
    int f = threadIdx.x;  // 0..511
    float sum = 0.f, mx = 0.f;
    for (int i = s; i < e; i++) {
        float v = x[(size_t)i * 512 + f];
        sum += v * g_gate[i];
        mx = fmaxf(mx, v);
    }
    g_pool[g * 1024 + f] = sum;          // weighted-sum half
    g_pool[g * 1024 + 512 + f] = mx;     // max half (post-ReLU x >= 0 == empty fill)
}

// ---------------------------------------------------------------------------
// Launch
// ---------------------------------------------------------------------------
extern "C" void kernel_launch(void* const* d_in, const int* in_sizes, int n_in,
                              void* d_out, int out_size) {
    const float* xin   = (const float*)d_in[0];
    const int*   ei    = (const int*)d_in[1];    // int32! (JAX x64 disabled)
    const int*   batch = (const int*)d_in[2];    // int32!
    const float* W1 = (const float*)d_in[3];
    const float* b1 = (const float*)d_in[4];
    const float* W2 = (const float*)d_in[5];
    const float* b2 = (const float*)d_in[6];
    const float* W3 = (const float*)d_in[7];
    const float* b3 = (const float*)d_in[8];
    const float* pw = (const float*)d_in[9];
    const float* pb = (const float*)d_in[10];
    const float* Wo = (const float*)d_in[11];
    const float* bo = (const float*)d_in[12];
    float* out = (float*)d_out;

    const int N = in_sizes[0] / 256;
    const int E = in_sizes[1] / 2;
    const int* src = ei;
    const int* dst = ei + E;

    float *p_h, *p_x, *p_pool;
    cudaGetSymbolAddress((void**)&p_h, g_h);
    cudaGetSymbolAddress((void**)&p_x, g_x);
    cudaGetSymbolAddress((void**)&p_pool, g_pool);

    // Degree & normalization (recomputed each launch; sums of 1.0f are exact)
    deg_init_k<<<(N + 255) / 256, 256>>>(N);
    deg_edge_k<<<(E + 255) / 256, 256>>>(dst, E);
    dis_k<<<(N + 255) / 256, 256>>>(N);

    // --- GCN layers ---
    struct { const float *W, *b; int fin, fout; } L[3] = {
        {W1, b1, 256, 256}, {W2, b2, 256, 256}, {W3, b3, 256, 512}};
    const float* cur = xin;
    for (int l = 0; l < 3; l++) {
        int fin = L[l].fin, fout = L[l].fout;
        dim3 grid(fout / BN, (N + BM - 1) / BM);
        sgemm_k<<<grid, 256>>>(cur, L[l].W, p_h, N, fout, fin, nullptr, 0);
        int nf4 = N * (fout >> 2);
        self_init_k<<<(nf4 + 255) / 256, 256>>>(p_h, p_x, N, fout);
        edge_agg_k<<<(E * 32 + 255) / 256, 256>>>(src, dst, p_h, p_x, E, fout);
        finalize_k<<<(nf4 + 255) / 256, 256>>>(p_x, L[l].b, N, fout);
        cur = p_x;
    }

    // --- Pooling ---
    gate_k<<<(N * 32 + 255) / 256, 256>>>(p_x, pw, pb, N);
    seg_init_k<<<(GCNT + 255) / 256, 256>>>(N);
    seg_bounds_k<<<(N + 255) / 256, 256>>>(batch, N);
    pool_k<<<GCNT, 512>>>(p_x);

    // --- Head: relu(pool @ Wo + bo) ---
    dim3 hgrid(FPOUT / BN, (GCNT + BM - 1) / BM);
    sgemm_k<<<hgrid, 256>>>(p_pool, Wo, out, GCNT, FPOUT, 1024, bo, 1);
}

// round 6
// speedup vs baseline: 1.4753x; 1.4753x over previous
#include <cuda_runtime.h>
#include <cuda_bf16.h>
#include <math.h>

// Fixed problem shapes
#define NMAX   50000
#define FMAX   512
#define GCNT   512
#define FPOUT  2048

// Scratch (device globals: no allocation allowed)
__device__ float g_h [(size_t)NMAX * FMAX];  // hh = (x@W)*dis[row]
__device__ float g_x [(size_t)NMAX * FMAX];  // activation ping
__device__ float g_x2[(size_t)NMAX * FMAX];  // activation pong
__device__ float g_deg[NMAX];
__device__ float g_dis[NMAX];
__device__ float g_gate[NMAX];
__device__ float g_pool[GCNT * 1024];
__device__ int   g_start[GCNT];
__device__ int   g_end[GCNT];

// ---------------------------------------------------------------------------
// Node-layer SGEMM, 128x128x8 tile, 8x8 microtile, double-buffered smem.
// Epilogue: hh[row] = acc * dis[row];  x0[row] = hh * dis[row]  (self-loop
// term: h/deg, since dis^2 = 1/deg).  x0 MUST NOT alias A.
// ---------------------------------------------------------------------------
#define SBM 128
#define SBN 128
#define SBK 8

__global__ void __launch_bounds__(256) sgemm128_node(
    const float* __restrict__ A, const float* __restrict__ B,
    float* __restrict__ hh, float* __restrict__ x0,
    int M, int N, int K)
{
    __shared__ float As[2][SBK][SBM];
    __shared__ float Bs[2][SBK][SBN];

    const int bm = blockIdx.y * SBM;
    const int bn = blockIdx.x * SBN;
    const int tid = threadIdx.x;

    const int a_row = tid >> 1;          // 0..127
    const int a_col = (tid & 1) << 2;    // 0 or 4
    const int b_row = tid >> 5;          // 0..7
    const int b_col = (tid & 31) << 2;   // 0..124

    const int tr = (tid >> 4) << 3;      // 0..120
    const int tc = (tid & 15) << 3;      // 0..120

    const int nT = K / SBK;

    {
        float4 av = make_float4(0.f, 0.f, 0.f, 0.f);
        if (bm + a_row < M)
            av = *(const float4*)(A + (size_t)(bm + a_row) * K + a_col);
        As[0][a_col + 0][a_row] = av.x;
        As[0][a_col + 1][a_row] = av.y;
        As[0][a_col + 2][a_row] = av.z;
        As[0][a_col + 3][a_row] = av.w;
        *(float4*)&Bs[0][b_row][b_col] =
            *(const float4*)(B + (size_t)b_row * N + bn + b_col);
    }
    __syncthreads();

    float acc[8][8] = {};

    for (int t = 0; t < nT; t++) {
        const int buf = t & 1;
        float4 av = make_float4(0.f, 0.f, 0.f, 0.f);
        float4 bv;
        const bool more = (t + 1 < nT);
        if (more) {
            int k0 = (t + 1) * SBK;
            if (bm + a_row < M)
                av = *(const float4*)(A + (size_t)(bm + a_row) * K + k0 + a_col);
            bv = *(const float4*)(B + (size_t)(k0 + b_row) * N + bn + b_col);
        }

#pragma unroll
        for (int kk = 0; kk < SBK; kk++) {
            float a[8], b[8];
            *(float4*)&a[0] = *(const float4*)&As[buf][kk][tr];
            *(float4*)&a[4] = *(const float4*)&As[buf][kk][tr + 4];
            *(float4*)&b[0] = *(const float4*)&Bs[buf][kk][tc];
            *(float4*)&b[4] = *(const float4*)&Bs[buf][kk][tc + 4];
#pragma unroll
            for (int i = 0; i < 8; i++)
#pragma unroll
                for (int j = 0; j < 8; j++)
                    acc[i][j] += a[i] * b[j];
        }

        if (more) {
            const int nbuf = buf ^ 1;
            As[nbuf][a_col + 0][a_row] = av.x;
            As[nbuf][a_col + 1][a_row] = av.y;
            As[nbuf][a_col + 2][a_row] = av.z;
            As[nbuf][a_col + 3][a_row] = av.w;
            *(float4*)&Bs[nbuf][b_row][b_col] = bv;
            __syncthreads();
        }
    }

#pragma unroll
    for (int i = 0; i < 8; i++) {
        int row = bm + tr + i;
        if (row >= M) break;
        float dr = g_dis[row];
        float* hr = hh + (size_t)row * N + bn + tc;
        float* xr = x0 + (size_t)row * N + bn + tc;
#pragma unroll
        for (int j4 = 0; j4 < 8; j4 += 4) {
            float4 hv, xv;
            hv.x = acc[i][j4 + 0] * dr; xv.x = hv.x * dr;
            hv.y = acc[i][j4 + 1] * dr; xv.y = hv.y * dr;
            hv.z = acc[i][j4 + 2] * dr; xv.z = hv.z * dr;
            hv.w = acc[i][j4 + 3] * dr; xv.w = hv.w * dr;
            *(float4*)(hr + j4) = hv;
            *(float4*)(xr + j4) = xv;
        }
    }
}

// ---------------------------------------------------------------------------
// 64x64 SGEMM (head: M=512, want 256 CTAs for occupancy)
// ---------------------------------------------------------------------------
#define BM 64
#define BN 64
#define BK 16

__global__ void __launch_bounds__(256) sgemm_k(
    const float* __restrict__ A, const float* __restrict__ B,
    float* __restrict__ C, int M, int N, int K,
    const float* __restrict__ bias, int dorelu)
{
    __shared__ float As[BK][BM];
    __shared__ float Bs[BK][BN];
    const int bm = blockIdx.y * BM;
    const int bn = blockIdx.x * BN;
    const int tid = threadIdx.x;
    const int tr = (tid >> 4) << 2;
    const int tc = (tid & 15) << 2;
    const int arow = tid >> 2;
    const int acol = (tid & 3) << 2;
    const int brow = tid >> 4;
    const int bcol = (tid & 15) << 2;

    float acc[4][4] = {};

    for (int k0 = 0; k0 < K; k0 += BK) {
        float4 av = make_float4(0.f, 0.f, 0.f, 0.f);
        if (bm + arow < M)
            av = *(const float4*)(A + (size_t)(bm + arow) * K + k0 + acol);
        As[acol + 0][arow] = av.x;
        As[acol + 1][arow] = av.y;
        As[acol + 2][arow] = av.z;
        As[acol + 3][arow] = av.w;
        *(float4*)&Bs[brow][bcol] =
            *(const float4*)(B + (size_t)(k0 + brow) * N + bn + bcol);
        __syncthreads();
#pragma unroll
        for (int k = 0; k < BK; k++) {
            float4 a = *(const float4*)&As[k][tr];
            float4 b = *(const float4*)&Bs[k][tc];
            acc[0][0] += a.x * b.x; acc[0][1] += a.x * b.y; acc[0][2] += a.x * b.z; acc[0][3] += a.x * b.w;
            acc[1][0] += a.y * b.x; acc[1][1] += a.y * b.y; acc[1][2] += a.y * b.z; acc[1][3] += a.y * b.w;
            acc[2][0] += a.z * b.x; acc[2][1] += a.z * b.y; acc[2][2] += a.z * b.z; acc[2][3] += a.z * b.w;
            acc[3][0] += a.w * b.x; acc[3][1] += a.w * b.y; acc[3][2] += a.w * b.z; acc[3][3] += a.w * b.w;
        }
        __syncthreads();
    }

#pragma unroll
    for (int i = 0; i < 4; i++) {
        int row = bm + tr + i;
        if (row >= M) break;
#pragma unroll
        for (int j = 0; j < 4; j++) {
            float v = acc[i][j];
            if (bias) v += bias[bn + tc + j];
            if (dorelu) v = fmaxf(v, 0.f);
            C[(size_t)row * N + bn + tc + j] = v;
        }
    }
}

// ---------------------------------------------------------------------------
// Degree / norm (int32 indices — JAX x64 disabled)
// ---------------------------------------------------------------------------
__global__ void deg_init_k(int n) {
    int i = blockIdx.x * blockDim.x + threadIdx.x;
    if (i < n) g_deg[i] = 1.0f;  // self-loop
}
__global__ void deg_edge_k(const int* __restrict__ dst, int e) {
    int i = blockIdx.x * blockDim.x + threadIdx.x;
    if (i < e) atomicAdd(&g_deg[dst[i]], 1.0f);
}
__global__ void dis_k(int n) {
    int i = blockIdx.x * blockDim.x + threadIdx.x;
    if (i < n) g_dis[i] = rsqrtf(g_deg[i]);
}

// ---------------------------------------------------------------------------
// Edge aggregation: out[d] += hh[s] * dis[d]   (hh already carries dis[s])
// ---------------------------------------------------------------------------
__device__ __forceinline__ void red_add_v4(float4* addr, float4 v) {
    asm volatile("red.global.add.v4.f32 [%0], {%1,%2,%3,%4};"
                 :: "l"(addr), "f"(v.x), "f"(v.y), "f"(v.z), "f"(v.w)
                 : "memory");
}

__global__ void edge_agg_k(const int* __restrict__ src,
                           const int* __restrict__ dst,
                           const float* __restrict__ hh, float* __restrict__ out,
                           int e, int f) {
    int w = (blockIdx.x * blockDim.x + threadIdx.x) >> 5;
    if (w >= e) return;
    int lane = threadIdx.x & 31;
    int s = src[w], d = dst[w];
    float nd = g_dis[d];
    const float4* hs = (const float4*)(hh + (size_t)s * f);
    float4* od = (float4*)(out + (size_t)d * f);
    int nf4 = f >> 2;
    for (int c = lane; c < nf4; c += 32) {
        float4 v = hs[c];
        v.x *= nd; v.y *= nd; v.z *= nd; v.w *= nd;
        red_add_v4(od + c, v);
    }
}

__global__ void finalize_k(float* __restrict__ out, const float* __restrict__ bias,
                           int n, int f) {
    int idx = blockIdx.x * blockDim.x + threadIdx.x;
    int nf4 = f >> 2;
    int total = n * nf4;
    if (idx >= total) return;
    int c4 = idx % nf4;
    float4 v = ((float4*)out)[idx];
    float4 b = ((const float4*)bias)[c4];
    v.x = fmaxf(v.x + b.x, 0.f);
    v.y = fmaxf(v.y + b.y, 0.f);
    v.z = fmaxf(v.z + b.z, 0.f);
    v.w = fmaxf(v.w + b.w, 0.f);
    ((float4*)out)[idx] = v;
}

// ---------------------------------------------------------------------------
// Gate: sigmoid(dot(x, pw) + pb)  (warp per node, F=512)
// ---------------------------------------------------------------------------
__global__ void gate_k(const float* __restrict__ x, const float* __restrict__ pw,
                       const float* __restrict__ pb, int n) {
    int w = (blockIdx.x * blockDim.x + threadIdx.x) >> 5;
    if (w >= n) return;
    int lane = threadIdx.x & 31;
    const float* row = x + (size_t)w * 512;
    float s = 0.f;
#pragma unroll
    for (int c = lane; c < 512; c += 32) s += row[c] * pw[c];
#pragma unroll
    for (int o = 16; o > 0; o >>= 1) s += __shfl_xor_sync(0xffffffffu, s, o);
    if (lane == 0) g_gate[w] = 1.f / (1.f + expf(-(s + pb[0])));
}

// ---------------------------------------------------------------------------
// Segment bounds + pooling
// ---------------------------------------------------------------------------
__global__ void seg_init_k(int n) {
    int g = blockIdx.x * blockDim.x + threadIdx.x;
    if (g < GCNT) { g_start[g] = n; g_end[g] = 0; }
}
__global__ void seg_bounds_k(const int* __restrict__ batch, int n) {
    int i = blockIdx.x * blockDim.x + threadIdx.x;
    if (i >= n) return;
    int g = batch[i];
    atomicMin(&g_start[g], i);
    atomicMax(&g_end[g], i + 1);
}
__global__ void __launch_bounds__(512) pool_k(const float* __restrict__ x) {
    int g = blockIdx.x;
    int s = g_start[g], e = g_end[g];
    int f = threadIdx.x;
    float sum = 0.f, mx = 0.f;
    for (int i = s; i < e; i++) {
        float v = x[(size_t)i * 512 + f];
        sum += v * g_gate[i];
        mx = fmaxf(mx, v);
    }
    g_pool[g * 1024 + f] = sum;
    g_pool[g * 1024 + 512 + f] = mx;  // post-ReLU x >= 0 == empty-segment fill
}

// ---------------------------------------------------------------------------
// Launch
// ---------------------------------------------------------------------------
extern "C" void kernel_launch(void* const* d_in, const int* in_sizes, int n_in,
                              void* d_out, int out_size) {
    const float* xin   = (const float*)d_in[0];
    const int*   ei    = (const int*)d_in[1];
    const int*   batch = (const int*)d_in[2];
    const float* W1 = (const float*)d_in[3];
    const float* b1 = (const float*)d_in[4];
    const float* W2 = (const float*)d_in[5];
    const float* b2 = (const float*)d_in[6];
    const float* W3 = (const float*)d_in[7];
    const float* b3 = (const float*)d_in[8];
    const float* pw = (const float*)d_in[9];
    const float* pb = (const float*)d_in[10];
    const float* Wo = (const float*)d_in[11];
    const float* bo = (const float*)d_in[12];
    float* out = (float*)d_out;

    const int N = in_sizes[0] / 256;
    const int E = in_sizes[1] / 2;
    const int* src = ei;
    const int* dst = ei + E;

    float *p_h, *p_xa, *p_xb, *p_pool;
    cudaGetSymbolAddress((void**)&p_h,  g_h);
    cudaGetSymbolAddress((void**)&p_xa, g_x);
    cudaGetSymbolAddress((void**)&p_xb, g_x2);
    cudaGetSymbolAddress((void**)&p_pool, g_pool);

    // Degree & normalization
    deg_init_k<<<(N + 255) / 256, 256>>>(N);
    deg_edge_k<<<(E + 255) / 256, 256>>>(dst, E);
    dis_k<<<(N + 255) / 256, 256>>>(N);

    // --- GCN layers (ping-pong activations: epilogue never aliases A) ---
    struct { const float *W, *b; int fin, fout; } L[3] = {
        {W1, b1, 256, 256}, {W2, b2, 256, 256}, {W3, b3, 256, 512}};
    const float* cur = xin;
    float* act[2] = {p_xa, p_xb};
    float* x_out = nullptr;
    for (int l = 0; l < 3; l++) {
        int fin = L[l].fin, fout = L[l].fout;
        x_out = act[l & 1];
        dim3 grid(fout / SBN, (N + SBM - 1) / SBM);
        sgemm128_node<<<grid, 256>>>(cur, L[l].W, p_h, x_out, N, fout, fin);
        edge_agg_k<<<(E * 32 + 255) / 256, 256>>>(src, dst, p_h, x_out, E, fout);
        int nf4 = N * (fout >> 2);
        finalize_k<<<(nf4 + 255) / 256, 256>>>(x_out, L[l].b, N, fout);
        cur = x_out;
    }

    // --- Pooling ---
    gate_k<<<(N * 32 + 255) / 256, 256>>>(x_out, pw, pb, N);
    seg_init_k<<<(GCNT + 255) / 256, 256>>>(N);
    seg_bounds_k<<<(N + 255) / 256, 256>>>(batch, N);
    pool_k<<<GCNT, 512>>>(x_out);

    // --- Head: relu(pool @ Wo + bo) ---
    dim3 hgrid(FPOUT / BN, (GCNT + BM - 1) / BM);
    sgemm_k<<<hgrid, 256>>>(p_pool, Wo, out, GCNT, FPOUT, 1024, bo, 1);
}

// round 7
// speedup vs baseline: 2.1910x; 1.4852x over previous
#include <cuda_runtime.h>
#include <cuda_bf16.h>
#include <math.h>

// Fixed problem shapes
#define NMAX   50000
#define EMAX   800000
#define FMAX   512
#define GCNT   512
#define FPOUT  2048

// Scratch (device globals: no allocation allowed)
__device__ float g_h [(size_t)NMAX * FMAX];  // hh = (x@W)*dis[row]
__device__ float g_x [(size_t)NMAX * FMAX];  // activation ping
__device__ float g_x2[(size_t)NMAX * FMAX];  // activation pong
__device__ float g_dis[NMAX];
__device__ float g_gate[NMAX];
__device__ float g_pool[GCNT * 1024];
__device__ int   g_cnt[NMAX];
__device__ int   g_rowptr[NMAX + 1];
__device__ int   g_fill[NMAX];
__device__ int   g_esrc[EMAX];
__device__ int   g_start[GCNT];
__device__ int   g_end[GCNT];

// ---------------------------------------------------------------------------
// Node-layer SGEMM, 128x128x8 tile, 8x8 microtile, double-buffered smem.
// Epilogue: hh[row] = acc * dis[row]   (only output; agg kernel does the rest)
// ---------------------------------------------------------------------------
#define SBM 128
#define SBN 128
#define SBK 8

__global__ void __launch_bounds__(256) sgemm128_node(
    const float* __restrict__ A, const float* __restrict__ B,
    float* __restrict__ hh, int M, int N, int K)
{
    __shared__ float As[2][SBK][SBM];
    __shared__ float Bs[2][SBK][SBN];

    const int bm = blockIdx.y * SBM;
    const int bn = blockIdx.x * SBN;
    const int tid = threadIdx.x;

    const int a_row = tid >> 1;          // 0..127
    const int a_col = (tid & 1) << 2;    // 0 or 4
    const int b_row = tid >> 5;          // 0..7
    const int b_col = (tid & 31) << 2;   // 0..124

    const int tr = (tid >> 4) << 3;      // 0..120
    const int tc = (tid & 15) << 3;      // 0..120

    const int nT = K / SBK;

    {
        float4 av = make_float4(0.f, 0.f, 0.f, 0.f);
        if (bm + a_row < M)
            av = *(const float4*)(A + (size_t)(bm + a_row) * K + a_col);
        As[0][a_col + 0][a_row] = av.x;
        As[0][a_col + 1][a_row] = av.y;
        As[0][a_col + 2][a_row] = av.z;
        As[0][a_col + 3][a_row] = av.w;
        *(float4*)&Bs[0][b_row][b_col] =
            *(const float4*)(B + (size_t)b_row * N + bn + b_col);
    }
    __syncthreads();

    float acc[8][8] = {};

    for (int t = 0; t < nT; t++) {
        const int buf = t & 1;
        float4 av = make_float4(0.f, 0.f, 0.f, 0.f);
        float4 bv;
        const bool more = (t + 1 < nT);
        if (more) {
            int k0 = (t + 1) * SBK;
            if (bm + a_row < M)
                av = *(const float4*)(A + (size_t)(bm + a_row) * K + k0 + a_col);
            bv = *(const float4*)(B + (size_t)(k0 + b_row) * N + bn + b_col);
        }

#pragma unroll
        for (int kk = 0; kk < SBK; kk++) {
            float a[8], b[8];
            *(float4*)&a[0] = *(const float4*)&As[buf][kk][tr];
            *(float4*)&a[4] = *(const float4*)&As[buf][kk][tr + 4];
            *(float4*)&b[0] = *(const float4*)&Bs[buf][kk][tc];
            *(float4*)&b[4] = *(const float4*)&Bs[buf][kk][tc + 4];
#pragma unroll
            for (int i = 0; i < 8; i++)
#pragma unroll
                for (int j = 0; j < 8; j++)
                    acc[i][j] += a[i] * b[j];
        }

        if (more) {
            const int nbuf = buf ^ 1;
            As[nbuf][a_col + 0][a_row] = av.x;
            As[nbuf][a_col + 1][a_row] = av.y;
            As[nbuf][a_col + 2][a_row] = av.z;
            As[nbuf][a_col + 3][a_row] = av.w;
            *(float4*)&Bs[nbuf][b_row][b_col] = bv;
            __syncthreads();
        }
    }

#pragma unroll
    for (int i = 0; i < 8; i++) {
        int row = bm + tr + i;
        if (row >= M) break;
        float dr = g_dis[row];
        float* hr = hh + (size_t)row * N + bn + tc;
#pragma unroll
        for (int j4 = 0; j4 < 8; j4 += 4) {
            float4 hv;
            hv.x = acc[i][j4 + 0] * dr;
            hv.y = acc[i][j4 + 1] * dr;
            hv.z = acc[i][j4 + 2] * dr;
            hv.w = acc[i][j4 + 3] * dr;
            *(float4*)(hr + j4) = hv;
        }
    }
}

// ---------------------------------------------------------------------------
// 64x64 SGEMM (head)
// ---------------------------------------------------------------------------
#define BM 64
#define BN 64
#define BK 16

__global__ void __launch_bounds__(256) sgemm_k(
    const float* __restrict__ A, const float* __restrict__ B,
    float* __restrict__ C, int M, int N, int K,
    const float* __restrict__ bias, int dorelu)
{
    __shared__ float As[BK][BM];
    __shared__ float Bs[BK][BN];
    const int bm = blockIdx.y * BM;
    const int bn = blockIdx.x * BN;
    const int tid = threadIdx.x;
    const int tr = (tid >> 4) << 2;
    const int tc = (tid & 15) << 2;
    const int arow = tid >> 2;
    const int acol = (tid & 3) << 2;
    const int brow = tid >> 4;
    const int bcol = (tid & 15) << 2;

    float acc[4][4] = {};

    for (int k0 = 0; k0 < K; k0 += BK) {
        float4 av = make_float4(0.f, 0.f, 0.f, 0.f);
        if (bm + arow < M)
            av = *(const float4*)(A + (size_t)(bm + arow) * K + k0 + acol);
        As[acol + 0][arow] = av.x;
        As[acol + 1][arow] = av.y;
        As[acol + 2][arow] = av.z;
        As[acol + 3][arow] = av.w;
        *(float4*)&Bs[brow][bcol] =
            *(const float4*)(B + (size_t)(k0 + brow) * N + bn + bcol);
        __syncthreads();
#pragma unroll
        for (int k = 0; k < BK; k++) {
            float4 a = *(const float4*)&As[k][tr];
            float4 b = *(const float4*)&Bs[k][tc];
            acc[0][0] += a.x * b.x; acc[0][1] += a.x * b.y; acc[0][2] += a.x * b.z; acc[0][3] += a.x * b.w;
            acc[1][0] += a.y * b.x; acc[1][1] += a.y * b.y; acc[1][2] += a.y * b.z; acc[1][3] += a.y * b.w;
            acc[2][0] += a.z * b.x; acc[2][1] += a.z * b.y; acc[2][2] += a.z * b.z; acc[2][3] += a.z * b.w;
            acc[3][0] += a.w * b.x; acc[3][1] += a.w * b.y; acc[3][2] += a.w * b.z; acc[3][3] += a.w * b.w;
        }
        __syncthreads();
    }

#pragma unroll
    for (int i = 0; i < 4; i++) {
        int row = bm + tr + i;
        if (row >= M) break;
#pragma unroll
        for (int j = 0; j < 4; j++) {
            float v = acc[i][j];
            if (bias) v += bias[bn + tc + j];
            if (dorelu) v = fmaxf(v, 0.f);
            C[(size_t)row * N + bn + tc + j] = v;
        }
    }
}

// ---------------------------------------------------------------------------
// CSR build: histogram by dst -> exclusive scan -> cursor scatter
// ---------------------------------------------------------------------------
__global__ void cnt_zero_k(int n) {
    int i = blockIdx.x * blockDim.x + threadIdx.x;
    if (i < n) g_cnt[i] = 0;
}
__global__ void hist_k(const int* __restrict__ dst, int e) {
    int i = blockIdx.x * blockDim.x + threadIdx.x;
    if (i < e) atomicAdd(&g_cnt[dst[i]], 1);
}
__global__ void dis_k(int n) {
    int i = blockIdx.x * blockDim.x + threadIdx.x;
    if (i < n) g_dis[i] = rsqrtf((float)(g_cnt[i] + 1));  // +1 self-loop
}

#define SCAN_T 1024
__global__ void __launch_bounds__(SCAN_T) scan_k(int n) {
    __shared__ int part[SCAN_T];
    int t = threadIdx.x;
    int chunk = (n + SCAN_T - 1) / SCAN_T;
    int lo = t * chunk;
    int hi = lo + chunk; if (hi > n) hi = n;
    int s = 0;
    for (int i = lo; i < hi; i++) s += g_cnt[i];
    part[t] = s;
    __syncthreads();
    for (int off = 1; off < SCAN_T; off <<= 1) {
        int v = (t >= off) ? part[t - off] : 0;
        __syncthreads();
        if (t >= off) part[t] += v;
        __syncthreads();
    }
    int base = (t == 0) ? 0 : part[t - 1];
    for (int i = lo; i < hi; i++) {
        g_rowptr[i] = base;
        g_fill[i] = base;
        base += g_cnt[i];
    }
    if (t == SCAN_T - 1) g_rowptr[n] = part[SCAN_T - 1];
}

__global__ void scatter_k(const int* __restrict__ src, const int* __restrict__ dst,
                          int e) {
    int i = blockIdx.x * blockDim.x + threadIdx.x;
    if (i >= e) return;
    int pos = atomicAdd(&g_fill[dst[i]], 1);
    g_esrc[pos] = src[i];
}

// ---------------------------------------------------------------------------
// Pull-aggregation (warp per node):
//   x_out[d] = relu(dis[d] * (hh[d] + sum_{s in in(d)} hh[s]) + bias)
// Optionally fuses the pooling gate: g_gate[d] = sigmoid(dot(x_out[d], pw)+pb)
// NF4 = float4 per lane (f = NF4*128): 2 for f=256, 4 for f=512.
// ---------------------------------------------------------------------------
template <int NF4>
__global__ void __launch_bounds__(256) agg_csr_k(
    const float* __restrict__ hh, float* __restrict__ xo,
    const float* __restrict__ bias, int n,
    const float* __restrict__ pw, const float* __restrict__ pb, int dogate)
{
    int w = (blockIdx.x * blockDim.x + threadIdx.x) >> 5;
    if (w >= n) return;
    const int lane = threadIdx.x & 31;
    const int f = NF4 * 128;

    float4 acc[NF4];
    const float4* hrow = (const float4*)(hh + (size_t)w * f);
#pragma unroll
    for (int j = 0; j < NF4; j++) acc[j] = hrow[j * 32 + lane];  // self term

    const int beg = g_rowptr[w], end = g_rowptr[w + 1];
    for (int e = beg; e < end; e++) {
        int s = g_esrc[e];
        const float4* hs = (const float4*)(hh + (size_t)s * f);
#pragma unroll
        for (int j = 0; j < NF4; j++) {
            float4 v = hs[j * 32 + lane];
            acc[j].x += v.x; acc[j].y += v.y; acc[j].z += v.z; acc[j].w += v.w;
        }
    }

    const float nd = g_dis[w];
    float4* xrow = (float4*)(xo + (size_t)w * f);
    float gdot = 0.f;
#pragma unroll
    for (int j = 0; j < NF4; j++) {
        float4 b = ((const float4*)bias)[j * 32 + lane];
        float4 o;
        o.x = fmaxf(fmaf(acc[j].x, nd, b.x), 0.f);
        o.y = fmaxf(fmaf(acc[j].y, nd, b.y), 0.f);
        o.z = fmaxf(fmaf(acc[j].z, nd, b.z), 0.f);
        o.w = fmaxf(fmaf(acc[j].w, nd, b.w), 0.f);
        xrow[j * 32 + lane] = o;
        if (dogate) {
            float4 p = ((const float4*)pw)[j * 32 + lane];
            gdot += o.x * p.x + o.y * p.y + o.z * p.z + o.w * p.w;
        }
    }
    if (dogate) {
#pragma unroll
        for (int off = 16; off > 0; off >>= 1)
            gdot += __shfl_xor_sync(0xffffffffu, gdot, off);
        if (lane == 0) g_gate[w] = 1.f / (1.f + expf(-(gdot + pb[0])));
    }
}

// ---------------------------------------------------------------------------
// Segment bounds + pooling
// ---------------------------------------------------------------------------
__global__ void seg_init_k(int n) {
    int g = blockIdx.x * blockDim.x + threadIdx.x;
    if (g < GCNT) { g_start[g] = n; g_end[g] = 0; }
}
__global__ void seg_bounds_k(const int* __restrict__ batch, int n) {
    int i = blockIdx.x * blockDim.x + threadIdx.x;
    if (i >= n) return;
    int g = batch[i];
    atomicMin(&g_start[g], i);
    atomicMax(&g_end[g], i + 1);
}
__global__ void __launch_bounds__(512) pool_k(const float* __restrict__ x) {
    int g = blockIdx.x;
    int s = g_start[g], e = g_end[g];
    int f = threadIdx.x;
    float sum = 0.f, mx = 0.f;
    for (int i = s; i < e; i++) {
        float v = x[(size_t)i * 512 + f];
        sum += v * g_gate[i];
        mx = fmaxf(mx, v);
    }
    g_pool[g * 1024 + f] = sum;
    g_pool[g * 1024 + 512 + f] = mx;  // post-ReLU x >= 0 == empty-segment fill
}

// ---------------------------------------------------------------------------
// Launch
// ---------------------------------------------------------------------------
extern "C" void kernel_launch(void* const* d_in, const int* in_sizes, int n_in,
                              void* d_out, int out_size) {
    const float* xin   = (const float*)d_in[0];
    const int*   ei    = (const int*)d_in[1];
    const int*   batch = (const int*)d_in[2];
    const float* W1 = (const float*)d_in[3];
    const float* b1 = (const float*)d_in[4];
    const float* W2 = (const float*)d_in[5];
    const float* b2 = (const float*)d_in[6];
    const float* W3 = (const float*)d_in[7];
    const float* b3 = (const float*)d_in[8];
    const float* pw = (const float*)d_in[9];
    const float* pb = (const float*)d_in[10];
    const float* Wo = (const float*)d_in[11];
    const float* bo = (const float*)d_in[12];
    float* out = (float*)d_out;

    const int N = in_sizes[0] / 256;
    const int E = in_sizes[1] / 2;
    const int* src = ei;
    const int* dst = ei + E;

    float *p_h, *p_xa, *p_xb, *p_pool;
    cudaGetSymbolAddress((void**)&p_h,  g_h);
    cudaGetSymbolAddress((void**)&p_xa, g_x);
    cudaGetSymbolAddress((void**)&p_xb, g_x2);
    cudaGetSymbolAddress((void**)&p_pool, g_pool);

    // CSR build + normalization
    cnt_zero_k<<<(N + 255) / 256, 256>>>(N);
    hist_k<<<(E + 255) / 256, 256>>>(dst, E);
    dis_k<<<(N + 255) / 256, 256>>>(N);
    scan_k<<<1, SCAN_T>>>(N);
    scatter_k<<<(E + 255) / 256, 256>>>(src, dst, E);

    // --- GCN layers ---
    struct { const float *W, *b; int fin, fout; } L[3] = {
        {W1, b1, 256, 256}, {W2, b2, 256, 256}, {W3, b3, 256, 512}};
    const float* cur = xin;
    float* act[2] = {p_xa, p_xb};
    float* x_out = nullptr;
    for (int l = 0; l < 3; l++) {
        int fin = L[l].fin, fout = L[l].fout;
        x_out = act[l & 1];
        dim3 grid(fout / SBN, (N + SBM - 1) / SBM);
        sgemm128_node<<<grid, 256>>>(cur, L[l].W, p_h, N, fout, fin);
        int aggblocks = (N * 32 + 255) / 256;
        if (fout == 256)
            agg_csr_k<2><<<aggblocks, 256>>>(p_h, x_out, L[l].b, N, pw, pb, 0);
        else
            agg_csr_k<4><<<aggblocks, 256>>>(p_h, x_out, L[l].b, N, pw, pb,
                                             (l == 2) ? 1 : 0);
        cur = x_out;
    }

    // --- Pooling ---
    seg_init_k<<<(GCNT + 255) / 256, 256>>>(N);
    seg_bounds_k<<<(N + 255) / 256, 256>>>(batch, N);
    pool_k<<<GCNT, 512>>>(x_out);

    // --- Head: relu(pool @ Wo + bo) ---
    dim3 hgrid(FPOUT / BN, (GCNT + BM - 1) / BM);
    sgemm_k<<<hgrid, 256>>>(p_pool, Wo, out, GCNT, FPOUT, 1024, bo, 1);
}

// round 11
// speedup vs baseline: 2.7312x; 1.2465x over previous
#include <cuda_runtime.h>
#include <cuda_bf16.h>
#include <math.h>
#include <stdint.h>

// Fixed problem shapes
#define NMAX   50000
#define EMAX   800000
#define FMAX   512
#define GCNT   512
#define FPOUT  2048

// Scratch (device globals: no allocation allowed)
__device__ float g_h [(size_t)NMAX * FMAX];  // hh = (x@W)*dis[row]
__device__ float g_x [(size_t)NMAX * FMAX];  // activation ping
__device__ float g_x2[(size_t)NMAX * FMAX];  // activation pong
__device__ float g_dis[NMAX];
__device__ float g_gate[NMAX];
__device__ float g_pool[GCNT * 1024];
__device__ int   g_cnt[NMAX];
__device__ int   g_rowptr[NMAX + 1];
__device__ int   g_fill[NMAX];
__device__ int   g_esrc[EMAX];
__device__ int   g_bsum[256];
__device__ int   g_start[GCNT];
__device__ int   g_end[GCNT];

__device__ __forceinline__ float to_tf32(float x) {
    uint32_t u;
    asm("cvt.rna.tf32.f32 %0, %1;" : "=r"(u) : "f"(x));
    return __uint_as_float(u);
}

__device__ __forceinline__ void mma_tf32(float* c, const uint32_t* a,
                                         uint32_t b0, uint32_t b1) {
    asm volatile(
        "mma.sync.aligned.m16n8k8.row.col.f32.tf32.tf32.f32 "
        "{%0,%1,%2,%3}, {%4,%5,%6,%7}, {%8,%9}, {%0,%1,%2,%3};"
        : "+f"(c[0]), "+f"(c[1]), "+f"(c[2]), "+f"(c[3])
        : "r"(a[0]), "r"(a[1]), "r"(a[2]), "r"(a[3]), "r"(b0), "r"(b1));
}

// ===========================================================================
// Node GEMM via mma.sync tf32, split precision (hi+lo), CTA 128x128, K-chunk 16.
//   hh[M, Nout] = (A[M,K] @ B[K,Nout]) * dis[row]
// 8 warps: warp tile 32(M) x 64(N) = 2 x 8 m16n8k8 atoms.
// ===========================================================================
#define CHK 16
#define PITCH 132

__global__ void __launch_bounds__(256, 2) gemm_mma_node(
    const float* __restrict__ A, const float* __restrict__ B,
    float* __restrict__ hh, int M, int Nout, int K)
{
    __shared__ __align__(16) float As_hi[CHK][PITCH];
    __shared__ __align__(16) float As_lo[CHK][PITCH];
    __shared__ __align__(16) float Bs_hi[CHK][PITCH];
    __shared__ __align__(16) float Bs_lo[CHK][PITCH];

    const int tid  = threadIdx.x;
    const int lane = tid & 31;
    const int wid  = tid >> 5;
    const int bm = blockIdx.y * 128;
    const int bn = blockIdx.x * 128;
    const int wm = (wid & 3) * 32;   // warp M offset in tile
    const int wn = (wid >> 2) * 64;  // warp N offset in tile
    const int q = lane >> 2;         // group id 0..7
    const int s = lane & 3;          // thread-in-group 0..3

    // global-load mapping
    const int a_row = tid >> 1;            // 0..127
    const int a_cb  = (tid & 1) * 8;       // 0 or 8
    const int b_k   = tid >> 4;            // 0..15
    const int b_n   = (tid & 15) * 8;      // 0..120

    float acc[2][8][4];
#pragma unroll
    for (int i = 0; i < 2; i++)
#pragma unroll
        for (int j = 0; j < 8; j++)
#pragma unroll
            for (int v = 0; v < 4; v++) acc[i][j][v] = 0.f;

    for (int k0 = 0; k0 < K; k0 += CHK) {
        // ---- A chunk 128x16 -> As[k][m] (transposed), split hi/lo ----
        {
            const int grow = bm + a_row;
#pragma unroll
            for (int h = 0; h < 2; h++) {
                const int c = a_cb + h * 4;
                float4 v = make_float4(0.f, 0.f, 0.f, 0.f);
                if (grow < M)
                    v = *(const float4*)(A + (size_t)grow * K + k0 + c);
                float hx = to_tf32(v.x), hy = to_tf32(v.y);
                float hz = to_tf32(v.z), hw = to_tf32(v.w);
                As_hi[c + 0][a_row] = hx; As_lo[c + 0][a_row] = to_tf32(v.x - hx);
                As_hi[c + 1][a_row] = hy; As_lo[c + 1][a_row] = to_tf32(v.y - hy);
                As_hi[c + 2][a_row] = hz; As_lo[c + 2][a_row] = to_tf32(v.z - hz);
                As_hi[c + 3][a_row] = hw; As_lo[c + 3][a_row] = to_tf32(v.w - hw);
            }
        }
        // ---- B chunk 16x128 -> Bs[k][n], split hi/lo ----
        {
#pragma unroll
            for (int h = 0; h < 2; h++) {
                const int n = b_n + h * 4;
                float4 v = *(const float4*)(B + (size_t)(k0 + b_k) * Nout + bn + n);
                float4 h4, l4;
                h4.x = to_tf32(v.x); l4.x = to_tf32(v.x - h4.x);
                h4.y = to_tf32(v.y); l4.y = to_tf32(v.y - h4.y);
                h4.z = to_tf32(v.z); l4.z = to_tf32(v.z - h4.z);
                h4.w = to_tf32(v.w); l4.w = to_tf32(v.w - h4.w);
                *(float4*)&Bs_hi[b_k][n] = h4;
                *(float4*)&Bs_lo[b_k][n] = l4;
            }
        }
        __syncthreads();

#pragma unroll
        for (int k8 = 0; k8 < CHK / 8; k8++) {
            const int kr0 = k8 * 8 + s;
            const int kr1 = kr0 + 4;
            uint32_t ah[2][4], al[2][4];
#pragma unroll
            for (int am = 0; am < 2; am++) {
                const int r0 = wm + am * 16 + q;
                ah[am][0] = __float_as_uint(As_hi[kr0][r0]);
                ah[am][1] = __float_as_uint(As_hi[kr0][r0 + 8]);
                ah[am][2] = __float_as_uint(As_hi[kr1][r0]);
                ah[am][3] = __float_as_uint(As_hi[kr1][r0 + 8]);
                al[am][0] = __float_as_uint(As_lo[kr0][r0]);
                al[am][1] = __float_as_uint(As_lo[kr0][r0 + 8]);
                al[am][2] = __float_as_uint(As_lo[kr1][r0]);
                al[am][3] = __float_as_uint(As_lo[kr1][r0 + 8]);
            }
#pragma unroll
            for (int an = 0; an < 8; an++) {
                const int n0 = wn + an * 8 + q;
                const uint32_t bh0 = __float_as_uint(Bs_hi[kr0][n0]);
                const uint32_t bh1 = __float_as_uint(Bs_hi[kr1][n0]);
                const uint32_t bl0 = __float_as_uint(Bs_lo[kr0][n0]);
                const uint32_t bl1 = __float_as_uint(Bs_lo[kr1][n0]);
#pragma unroll
                for (int am = 0; am < 2; am++) {
                    mma_tf32(acc[am][an], ah[am], bh0, bh1);
                    mma_tf32(acc[am][an], al[am], bh0, bh1);
                    mma_tf32(acc[am][an], ah[am], bl0, bl1);
                }
            }
        }
        __syncthreads();
    }

    // ---- epilogue: hh = acc * dis[row] ----
#pragma unroll
    for (int am = 0; am < 2; am++) {
        const int row0 = bm + wm + am * 16 + q;
        const int row1 = row0 + 8;
        const float d0 = (row0 < M) ? g_dis[row0] : 0.f;
        const float d1 = (row1 < M) ? g_dis[row1] : 0.f;
#pragma unroll
        for (int an = 0; an < 8; an++) {
            const int col = bn + wn + an * 8 + s * 2;
            if (row0 < M) {
                float2 o = make_float2(acc[am][an][0] * d0, acc[am][an][1] * d0);
                *(float2*)(hh + (size_t)row0 * Nout + col) = o;
            }
            if (row1 < M) {
                float2 o = make_float2(acc[am][an][2] * d1, acc[am][an][3] * d1);
                *(float2*)(hh + (size_t)row1 * Nout + col) = o;
            }
        }
    }
}

// ---------------------------------------------------------------------------
// 64x64 SGEMM (head)
// ---------------------------------------------------------------------------
#define BM 64
#define BN 64
#define BK 16

__global__ void __launch_bounds__(256) sgemm_k(
    const float* __restrict__ A, const float* __restrict__ B,
    float* __restrict__ C, int M, int N, int K,
    const float* __restrict__ bias, int dorelu)
{
    __shared__ float As[BK][BM];
    __shared__ float Bs[BK][BN];
    const int bm = blockIdx.y * BM;
    const int bn = blockIdx.x * BN;
    const int tid = threadIdx.x;
    const int tr = (tid >> 4) << 2;
    const int tc = (tid & 15) << 2;
    const int arow = tid >> 2;
    const int acol = (tid & 3) << 2;
    const int brow = tid >> 4;
    const int bcol = (tid & 15) << 2;

    float acc[4][4] = {};

    for (int k0 = 0; k0 < K; k0 += BK) {
        float4 av = make_float4(0.f, 0.f, 0.f, 0.f);
        if (bm + arow < M)
            av = *(const float4*)(A + (size_t)(bm + arow) * K + k0 + acol);
        As[acol + 0][arow] = av.x;
        As[acol + 1][arow] = av.y;
        As[acol + 2][arow] = av.z;
        As[acol + 3][arow] = av.w;
        *(float4*)&Bs[brow][bcol] =
            *(const float4*)(B + (size_t)(k0 + brow) * N + bn + bcol);
        __syncthreads();
#pragma unroll
        for (int k = 0; k < BK; k++) {
            float4 a = *(const float4*)&As[k][tr];
            float4 b = *(const float4*)&Bs[k][tc];
            acc[0][0] += a.x * b.x; acc[0][1] += a.x * b.y; acc[0][2] += a.x * b.z; acc[0][3] += a.x * b.w;
            acc[1][0] += a.y * b.x; acc[1][1] += a.y * b.y; acc[1][2] += a.y * b.z; acc[1][3] += a.y * b.w;
            acc[2][0] += a.z * b.x; acc[2][1] += a.z * b.y; acc[2][2] += a.z * b.z; acc[2][3] += a.z * b.w;
            acc[3][0] += a.w * b.x; acc[3][1] += a.w * b.y; acc[3][2] += a.w * b.z; acc[3][3] += a.w * b.w;
        }
        __syncthreads();
    }

#pragma unroll
    for (int i = 0; i < 4; i++) {
        int row = bm + tr + i;
        if (row >= M) break;
#pragma unroll
        for (int j = 0; j < 4; j++) {
            float v = acc[i][j];
            if (bias) v += bias[bn + tc + j];
            if (dorelu) v = fmaxf(v, 0.f);
            C[(size_t)row * N + bn + tc + j] = v;
        }
    }
}

// ---------------------------------------------------------------------------
// CSR build: histogram -> 3-pass parallel scan -> cursor scatter
// ---------------------------------------------------------------------------
__global__ void cnt_zero_k(int n) {
    int i = blockIdx.x * blockDim.x + threadIdx.x;
    if (i < n) g_cnt[i] = 0;
}
__global__ void hist_k(const int* __restrict__ dst, int e) {
    int i = blockIdx.x * blockDim.x + threadIdx.x;
    if (i < e) atomicAdd(&g_cnt[dst[i]], 1);
}
__global__ void dis_k(int n) {
    int i = blockIdx.x * blockDim.x + threadIdx.x;
    if (i < n) g_dis[i] = rsqrtf((float)(g_cnt[i] + 1));  // +1 self-loop
}
__global__ void scan1_k(int n) {
    __shared__ int sh[256];
    int i = blockIdx.x * 256 + threadIdx.x;
    sh[threadIdx.x] = (i < n) ? g_cnt[i] : 0;
    __syncthreads();
    for (int o = 128; o > 0; o >>= 1) {
        if (threadIdx.x < o) sh[threadIdx.x] += sh[threadIdx.x + o];
        __syncthreads();
    }
    if (threadIdx.x == 0) g_bsum[blockIdx.x] = sh[0];
}
__global__ void scan2_k(int nb, int n) {
    __shared__ int sh[256];
    int t = threadIdx.x;
    int v = (t < nb) ? g_bsum[t] : 0;
    sh[t] = v; __syncthreads();
    for (int o = 1; o < 256; o <<= 1) {
        int u = (t >= o) ? sh[t - o] : 0;
        __syncthreads();
        sh[t] += u;
        __syncthreads();
    }
    if (t < nb) g_bsum[t] = sh[t] - v;  // exclusive
    if (t == 255) g_rowptr[n] = sh[255];
}
__global__ void scan3_k(int n) {
    __shared__ int sh[256];
    int t = threadIdx.x;
    int i = blockIdx.x * 256 + t;
    int v = (i < n) ? g_cnt[i] : 0;
    sh[t] = v; __syncthreads();
    for (int o = 1; o < 256; o <<= 1) {
        int u = (t >= o) ? sh[t - o] : 0;
        __syncthreads();
        sh[t] += u;
        __syncthreads();
    }
    if (i < n) {
        int off = g_bsum[blockIdx.x] + sh[t] - v;
        g_rowptr[i] = off;
        g_fill[i] = off;
    }
}
__global__ void scatter_k(const int* __restrict__ src, const int* __restrict__ dst,
                          int e) {
    int i = blockIdx.x * blockDim.x + threadIdx.x;
    if (i >= e) return;
    int pos = atomicAdd(&g_fill[dst[i]], 1);
    g_esrc[pos] = src[i];
}

// ---------------------------------------------------------------------------
// Pull-aggregation (warp per node):
//   x_out[d] = relu(dis[d] * (hh[d] + sum_{s in in(d)} hh[s]) + bias)
// Optional fused gate: g_gate[d] = sigmoid(dot(x_out[d], pw)+pb)
// ---------------------------------------------------------------------------
template <int NF4>
__global__ void __launch_bounds__(256) agg_csr_k(
    const float* __restrict__ hh, float* __restrict__ xo,
    const float* __restrict__ bias, int n,
    const float* __restrict__ pw, const float* __restrict__ pb, int dogate)
{
    int w = (blockIdx.x * blockDim.x + threadIdx.x) >> 5;
    if (w >= n) return;
    const int lane = threadIdx.x & 31;
    const int f = NF4 * 128;

    float4 acc[NF4];
    const float4* hrow = (const float4*)(hh + (size_t)w * f);
#pragma unroll
    for (int j = 0; j < NF4; j++) acc[j] = hrow[j * 32 + lane];  // self term

    const int beg = g_rowptr[w], end = g_rowptr[w + 1];
    for (int e = beg; e < end; e++) {
        int s = g_esrc[e];
        const float4* hs = (const float4*)(hh + (size_t)s * f);
#pragma unroll
        for (int j = 0; j < NF4; j++) {
            float4 v = hs[j * 32 + lane];
            acc[j].x += v.x; acc[j].y += v.y; acc[j].z += v.z; acc[j].w += v.w;
        }
    }

    const float nd = g_dis[w];
    float4* xrow = (float4*)(xo + (size_t)w * f);
    float gdot = 0.f;
#pragma unroll
    for (int j = 0; j < NF4; j++) {
        float4 b = ((const float4*)bias)[j * 32 + lane];
        float4 o;
        o.x = fmaxf(fmaf(acc[j].x, nd, b.x), 0.f);
        o.y = fmaxf(fmaf(acc[j].y, nd, b.y), 0.f);
        o.z = fmaxf(fmaf(acc[j].z, nd, b.z), 0.f);
        o.w = fmaxf(fmaf(acc[j].w, nd, b.w), 0.f);
        xrow[j * 32 + lane] = o;
        if (dogate) {
            float4 p = ((const float4*)pw)[j * 32 + lane];
            gdot += o.x * p.x + o.y * p.y + o.z * p.z + o.w * p.w;
        }
    }
    if (dogate) {
#pragma unroll
        for (int off = 16; off > 0; off >>= 1)
            gdot += __shfl_xor_sync(0xffffffffu, gdot, off);
        if (lane == 0) g_gate[w] = 1.f / (1.f + expf(-(gdot + pb[0])));
    }
}

// ---------------------------------------------------------------------------
// Segment bounds + pooling
// ---------------------------------------------------------------------------
__global__ void seg_init_k(int n) {
    int g = blockIdx.x * blockDim.x + threadIdx.x;
    if (g < GCNT) { g_start[g] = n; g_end[g] = 0; }
}
__global__ void seg_bounds_k(const int* __restrict__ batch, int n) {
    int i = blockIdx.x * blockDim.x + threadIdx.x;
    if (i >= n) return;
    int g = batch[i];
    atomicMin(&g_start[g], i);
    atomicMax(&g_end[g], i + 1);
}
__global__ void __launch_bounds__(512) pool_k(const float* __restrict__ x) {
    int g = blockIdx.x;
    int s = g_start[g], e = g_end[g];
    int f = threadIdx.x;
    float sum = 0.f, mx = 0.f;
    for (int i = s; i < e; i++) {
        float v = x[(size_t)i * 512 + f];
        sum += v * g_gate[i];
        mx = fmaxf(mx, v);
    }
    g_pool[g * 1024 + f] = sum;
    g_pool[g * 1024 + 512 + f] = mx;  // post-ReLU x >= 0 == empty-segment fill
}

// ---------------------------------------------------------------------------
// Launch
// ---------------------------------------------------------------------------
extern "C" void kernel_launch(void* const* d_in, const int* in_sizes, int n_in,
                              void* d_out, int out_size) {
    const float* xin   = (const float*)d_in[0];
    const int*   ei    = (const int*)d_in[1];
    const int*   batch = (const int*)d_in[2];
    const float* W1 = (const float*)d_in[3];
    const float* b1 = (const float*)d_in[4];
    const float* W2 = (const float*)d_in[5];
    const float* b2 = (const float*)d_in[6];
    const float* W3 = (const float*)d_in[7];
    const float* b3 = (const float*)d_in[8];
    const float* pw = (const float*)d_in[9];
    const float* pb = (const float*)d_in[10];
    const float* Wo = (const float*)d_in[11];
    const float* bo = (const float*)d_in[12];
    float* out = (float*)d_out;

    const int N = in_sizes[0] / 256;
    const int E = in_sizes[1] / 2;
    const int* src = ei;
    const int* dst = ei + E;

    float *p_h, *p_xa, *p_xb, *p_pool;
    cudaGetSymbolAddress((void**)&p_h,  g_h);
    cudaGetSymbolAddress((void**)&p_xa, g_x);
    cudaGetSymbolAddress((void**)&p_xb, g_x2);
    cudaGetSymbolAddress((void**)&p_pool, g_pool);

    // CSR build + normalization
    const int nb = (N + 255) / 256;
    cnt_zero_k<<<nb, 256>>>(N);
    hist_k<<<(E + 255) / 256, 256>>>(dst, E);
    dis_k<<<nb, 256>>>(N);
    scan1_k<<<nb, 256>>>(N);
    scan2_k<<<1, 256>>>(nb, N);
    scan3_k<<<nb, 256>>>(N);
    scatter_k<<<(E + 255) / 256, 256>>>(src, dst, E);

    // --- GCN layers ---
    struct { const float *W, *b; int fin, fout; } L[3] = {
        {W1, b1, 256, 256}, {W2, b2, 256, 256}, {W3, b3, 256, 512}};
    const float* cur = xin;
    float* act[2] = {p_xa, p_xb};
    float* x_out = nullptr;
    for (int l = 0; l < 3; l++) {
        int fin = L[l].fin, fout = L[l].fout;
        x_out = act[l & 1];
        dim3 grid(fout / 128, (N + 127) / 128);
        gemm_mma_node<<<grid, 256>>>(cur, L[l].W, p_h, N, fout, fin);
        int aggblocks = (N * 32 + 255) / 256;
        if (fout == 256)
            agg_csr_k<2><<<aggblocks, 256>>>(p_h, x_out, L[l].b, N, pw, pb, 0);
        else
            agg_csr_k<4><<<aggblocks, 256>>>(p_h, x_out, L[l].b, N, pw, pb,
                                             (l == 2) ? 1 : 0);
        cur = x_out;
    }

    // --- Pooling ---
    seg_init_k<<<(GCNT + 255) / 256, 256>>>(N);
    seg_bounds_k<<<nb, 256>>>(batch, N);
    pool_k<<<GCNT, 512>>>(x_out);

    // --- Head: relu(pool @ Wo + bo) ---
    dim3 hgrid(FPOUT / BN, (GCNT + BM - 1) / BM);
    sgemm_k<<<hgrid, 256>>>(p_pool, Wo, out, GCNT, FPOUT, 1024, bo, 1);
}